// round 9
// baseline (speedup 1.0000x reference)
#include <cuda_runtime.h>
#include <cstddef>

#define NB    16
#define HH    512
#define WWID  512
#define NPB   20000
#define NPTS  (NB * NPB)          // 320000
#define EPSV  1e-5f
#define NBLK  1250                // NPTS / 256 exactly

// ---------------- scratch ----------------
__device__ int g_map[NB * HH * WWID + 8];          // i+1 encoding; 0 = empty (zero-init; stays valid across replays)
__device__ int g_nbr_i[9 * NPTS];                  // i-space tap list (slot-major)
__device__ int g_cntv[NPTS];
__device__ int g_hist[NBLK * 10];
__device__ int g_boff[NBLK * 10];
__device__ int g_binbase[10];
__device__ int g_perm[NPTS];                       // pos -> i
__device__ int g_inv[NPTS];                        // i -> pos
__device__ int g_cntp[NPTS];                       // cnt by pos
__device__ int g_bpos[NPTS];                       // batch by pos
__device__ int g_nbr_p[9 * NPTS];                  // pos-space tap list (jp<<4 | tap)
__device__ __align__(16) float g_y1[NPTS * 8];     // pos-space
__device__ __align__(16) float g_y2[NPTS * 16];    // pos-space
__device__ __align__(16) float g_y3[NPTS * 32];    // pos-space
__device__ float g_part[NBLK * 64];                // [sum(C) | sumsq(C)] rows
__device__ float g_bn1[16], g_bn2[32], g_bn3[64];  // folded scale | shift
__device__ unsigned g_pool[NB * 32];
__device__ unsigned g_ctr[4];

// ---------------- block stats -> g_part row ----------------
template <int NCH>
__device__ __forceinline__ void block_stats(const float* acc, int blk) {
    __shared__ float s_red[8 * 2 * NCH];
    int lane = threadIdx.x & 31, warp = threadIdx.x >> 5;
#pragma unroll
    for (int co = 0; co < NCH; co++) {
        float s = acc[co], q = acc[co] * acc[co];
#pragma unroll
        for (int off = 16; off; off >>= 1) {
            s += __shfl_down_sync(0xffffffffu, s, off);
            q += __shfl_down_sync(0xffffffffu, q, off);
        }
        if (lane == 0) { s_red[warp * 2 * NCH + co] = s; s_red[warp * 2 * NCH + NCH + co] = q; }
    }
    __syncthreads();
    if (threadIdx.x < 2 * NCH) {
        float t = 0.f;
#pragma unroll
        for (int w = 0; w < 8; w++) t += s_red[w * 2 * NCH + threadIdx.x];
        g_part[blk * 64 + threadIdx.x] = t;
    }
}

// ---------------- gated-last-block BN fold (reads all NBLK g_part rows) ----------
template <int C>
__device__ __forceinline__ void fold_bn(const float* __restrict__ gamma,
                                        const float* __restrict__ beta,
                                        float* __restrict__ bn) {
    __shared__ float s4[4][64];
    int c = threadIdx.x & 63, seg = threadIdx.x >> 6;
    float a = 0.f;
    if (c < 2 * C)
        for (int r = seg; r < NBLK; r += 4) a += __ldcg(&g_part[r * 64 + c]);
    s4[seg][c] = a;
    __syncthreads();
    if ((int)threadIdx.x < C) {
        int c0 = threadIdx.x;
        float S = s4[0][c0] + s4[1][c0] + s4[2][c0] + s4[3][c0];
        float Q = s4[0][C + c0] + s4[1][C + c0] + s4[2][C + c0] + s4[3][C + c0];
        float m = S / (float)NPTS;
        float var = Q / (float)NPTS - m * m;
        float sc = gamma[c0] * rsqrtf(var + EPSV);
        bn[c0] = sc;
        bn[C + c0] = beta[c0] - m * sc;
    }
}

#define LAST_BLOCK_GATE(ctr, target, lastvar)                        \
    __threadfence();                                                 \
    __syncthreads();                                                 \
    if (threadIdx.x == 0)                                            \
        lastvar = (atomicAdd(&(ctr), 1u) == (unsigned)(target) - 1u);\
    __syncthreads();

// ---------------- 1: scatter (i+1) + clear pool/ctr ----------------
__global__ void k_scatter(const int* __restrict__ idx) {
    int i = blockIdx.x * blockDim.x + threadIdx.x;
    if (i < NPTS) {
        int b = idx[3 * i], y = idx[3 * i + 1], x = idx[3 * i + 2];
        g_map[(b << 18) | (y << 9) | x] = i + 1;
    }
    if (i < NB * 32) g_pool[i] = 0u;
    if (i < 4) g_ctr[i] = 0u;
}

// ---------------- 2: probe 9 cells -> i-space tap list + hist; last block scans ---
__global__ __launch_bounds__(256)
void k_probe(const int* __restrict__ idx) {
    __shared__ int hist[10];
    __shared__ bool s_last;
    if (threadIdx.x < 10) hist[threadIdx.x] = 0;
    __syncthreads();

    int i = blockIdx.x * 256 + threadIdx.x;
    int b = idx[3 * i], y = idx[3 * i + 1], x = idx[3 * i + 2];
    int base = b << 18;

    int jj[9];
#pragma unroll
    for (int t = 0; t < 9; t++) {
        int ny = y + t / 3 - 1, nx = x + t % 3 - 1;
        bool ok = ((unsigned)ny < (unsigned)HH) && ((unsigned)nx < (unsigned)WWID);
        int nyc = ok ? ny : y, nxc = ok ? nx : x;
        int j = g_map[base + (nyc << 9) + nxc];
        jj[t] = ok ? (j - 1) : -1;
    }
    int cnt = 0;
#pragma unroll
    for (int t = 0; t < 9; t++) {
        if (jj[t] >= 0) {
            g_nbr_i[cnt * NPTS + i] = (jj[t] << 4) | t;
            cnt++;
        }
    }
    g_cntv[i] = cnt;
    atomicAdd(&hist[cnt], 1);
    __syncthreads();
    if (threadIdx.x < 10) g_hist[blockIdx.x * 10 + threadIdx.x] = hist[threadIdx.x];

    LAST_BLOCK_GATE(g_ctr[0], NBLK, s_last);
    if (!s_last) return;

    // scan histograms (10 bins x NBLK) -> per-block offsets + bin bases
    __shared__ int s_tot[10];
    int warp = threadIdx.x >> 5, lane = threadIdx.x & 31;
    for (int k = warp; k < 10; k += 8) {
        int running = 0;
        for (int basei = 0; basei < NBLK; basei += 32) {
            int bb = basei + lane;
            int v = (bb < NBLK) ? __ldcg(&g_hist[bb * 10 + k]) : 0;
            int inc = v;
#pragma unroll
            for (int off = 1; off < 32; off <<= 1) {
                int n = __shfl_up_sync(0xffffffffu, inc, off);
                if (lane >= off) inc += n;
            }
            if (bb < NBLK) g_boff[bb * 10 + k] = running + (inc - v);
            running += __shfl_sync(0xffffffffu, inc, 31);
        }
        if (lane == 0) s_tot[k] = running;
    }
    __syncthreads();
    if (threadIdx.x == 0) {
        int r = 0;
#pragma unroll
        for (int kk = 0; kk < 10; kk++) { g_binbase[kk] = r; r += s_tot[kk]; }
    }
}

// ---------------- 3: deterministic rank -> perm / inv / cntp / bpos ----------------
__global__ __launch_bounds__(256)
void k_rank(const int* __restrict__ idx) {
    __shared__ int wcnt[8][10], wbase[8][10];
    int warp = threadIdx.x >> 5, lane = threadIdx.x & 31;
    if (threadIdx.x < 80) wcnt[threadIdx.x / 10][threadIdx.x % 10] = 0;
    __syncthreads();

    int i = blockIdx.x * 256 + threadIdx.x;
    int k = g_cntv[i];
    unsigned mymask = __match_any_sync(0xffffffffu, k);
    int lrank = __popc(mymask & ((1u << lane) - 1u));
    if (lane == (__ffs(mymask) - 1)) wcnt[warp][k] = __popc(mymask);
    __syncthreads();
    if (threadIdx.x < 80) {
        int w = threadIdx.x / 10, kk = threadIdx.x % 10;
        int s = 0;
        for (int w2 = 0; w2 < w; w2++) s += wcnt[w2][kk];
        wbase[w][kk] = s;
    }
    __syncthreads();
    int pos = g_binbase[k] + g_boff[blockIdx.x * 10 + k] + wbase[warp][k] + lrank;
    g_perm[pos] = i;
    g_inv[i] = pos;
    g_cntp[pos] = k;
    g_bpos[pos] = idx[3 * i];
}

// ---------------- 4: conv1 + remap tap list into pos-space; gate -> BN1 -----------
__global__ __launch_bounds__(256, 4)
void k_conv1(const float* __restrict__ feats, const float* __restrict__ w1,
             const float* __restrict__ g1, const float* __restrict__ b1)
{
    __shared__ float ws[72];
    __shared__ bool s_last;
    if (threadIdx.x < 72) ws[threadIdx.x] = w1[threadIdx.x];
    __syncthreads();

    int pos = blockIdx.x * 256 + threadIdx.x;
    int i = g_perm[pos];
    int cnt = g_cntp[pos];

    float acc[8];
#pragma unroll
    for (int c = 0; c < 8; c++) acc[c] = 0.f;

    for (int s = 0; s < cnt; s++) {
        int p = g_nbr_i[s * NPTS + i];        // scattered (one-time remap cost)
        int j = p >> 4, tap = p & 15;
        int jp = g_inv[j];                    // scattered
        g_nbr_p[s * NPTS + pos] = (jp << 4) | tap;   // coalesced
        float v = feats[j];                   // scattered
#pragma unroll
        for (int co = 0; co < 8; co++)
            acc[co] = fmaf(v, ws[tap * 8 + co], acc[co]);
    }

    float4* orow = reinterpret_cast<float4*>(g_y1 + (size_t)pos * 8);
    orow[0] = make_float4(acc[0], acc[1], acc[2], acc[3]);
    orow[1] = make_float4(acc[4], acc[5], acc[6], acc[7]);

    block_stats<8>(acc, blockIdx.x);
    LAST_BLOCK_GATE(g_ctr[1], NBLK, s_last);
    if (s_last) fold_bn<8>(g1, b1, g_bn1);
}

// ---------------- 5: conv2 (8->16), fully pos-space; gate -> BN2 ----------------
__global__ __launch_bounds__(256, 4)
void k_conv2(const float* __restrict__ w2,
             const float* __restrict__ g2, const float* __restrict__ b2)
{
    __shared__ float s_ws[9 * 8 * 16];
    __shared__ float s_ab[16];
    __shared__ bool s_last;
    for (int t = threadIdx.x; t < 9 * 8 * 16; t += 256) s_ws[t] = w2[t];
    if (threadIdx.x < 16) s_ab[threadIdx.x] = g_bn1[threadIdx.x];
    __syncthreads();

    int pos = blockIdx.x * 256 + threadIdx.x;
    int cnt = g_cntp[pos];                    // coalesced; uniform within warp
    float acc[16];
#pragma unroll
    for (int c = 0; c < 16; c++) acc[c] = 0.f;

    int pcur = g_nbr_p[pos];                  // coalesced
    for (int s = 0; s < cnt; s++) {
        int pnext = (s + 1 < cnt) ? g_nbr_p[(s + 1) * NPTS + pos] : 0;
        int jp = pcur >> 4, tp = pcur & 15;
        const float4* inr = reinterpret_cast<const float4*>(g_y1 + (size_t)jp * 8);
        float4 r0 = inr[0], r1 = inr[1];      // scattered gather (inherent)
        const float* wr = s_ws + tp * 128;
        float vv[8] = {r0.x, r0.y, r0.z, r0.w, r1.x, r1.y, r1.z, r1.w};
#pragma unroll
        for (int ci = 0; ci < 8; ci++) {
            float v = fmaxf(fmaf(vv[ci], s_ab[ci], s_ab[8 + ci]), 0.f);
#pragma unroll
            for (int co = 0; co < 16; co++)
                acc[co] = fmaf(v, wr[ci * 16 + co], acc[co]);
        }
        pcur = pnext;
    }

    float4* orow = reinterpret_cast<float4*>(g_y2 + (size_t)pos * 16);  // coalesced
#pragma unroll
    for (int c4 = 0; c4 < 4; c4++)
        orow[c4] = make_float4(acc[4 * c4], acc[4 * c4 + 1], acc[4 * c4 + 2], acc[4 * c4 + 3]);

    block_stats<16>(acc, blockIdx.x);
    LAST_BLOCK_GATE(g_ctr[2], NBLK, s_last);
    if (s_last) fold_bn<16>(g2, b2, g_bn2);
}

// ---------------- 6: conv3 (16->32), fully pos-space; gate -> BN3 ----------------
__global__ __launch_bounds__(256, 3)
void k_conv3(const float* __restrict__ w3,
             const float* __restrict__ g3, const float* __restrict__ b3)
{
    __shared__ float s_ws[9 * 16 * 32];
    __shared__ float s_ab[32];
    __shared__ bool s_last;
    for (int t = threadIdx.x; t < 9 * 16 * 32; t += 256) s_ws[t] = w3[t];
    if (threadIdx.x < 32) s_ab[threadIdx.x] = g_bn2[threadIdx.x];
    __syncthreads();

    int pos = blockIdx.x * 256 + threadIdx.x;
    int cnt = g_cntp[pos];
    float acc[32];
#pragma unroll
    for (int c = 0; c < 32; c++) acc[c] = 0.f;

    int pcur = g_nbr_p[pos];
    for (int s = 0; s < cnt; s++) {
        int pnext = (s + 1 < cnt) ? g_nbr_p[(s + 1) * NPTS + pos] : 0;
        int jp = pcur >> 4, tp = pcur & 15;
        const float4* inr = reinterpret_cast<const float4*>(g_y2 + (size_t)jp * 16);
        float4 r0 = inr[0], r1 = inr[1], r2 = inr[2], r3 = inr[3];
        const float* wr = s_ws + tp * 512;
        float vv[16] = {r0.x, r0.y, r0.z, r0.w, r1.x, r1.y, r1.z, r1.w,
                        r2.x, r2.y, r2.z, r2.w, r3.x, r3.y, r3.z, r3.w};
#pragma unroll
        for (int ci = 0; ci < 16; ci++) {
            float v = fmaxf(fmaf(vv[ci], s_ab[ci], s_ab[16 + ci]), 0.f);
#pragma unroll
            for (int co = 0; co < 32; co++)
                acc[co] = fmaf(v, wr[ci * 32 + co], acc[co]);
        }
        pcur = pnext;
    }

    float4* orow = reinterpret_cast<float4*>(g_y3 + (size_t)pos * 32);  // coalesced
#pragma unroll
    for (int c4 = 0; c4 < 8; c4++)
        orow[c4] = make_float4(acc[4 * c4], acc[4 * c4 + 1], acc[4 * c4 + 2], acc[4 * c4 + 3]);

    block_stats<32>(acc, blockIdx.x);
    LAST_BLOCK_GATE(g_ctr[3], NBLK, s_last);
    if (s_last) fold_bn<32>(g3, b3, g_bn3);
}

// ---------------- 7: pool (pos-space, per-block smem max table) ----------------
__global__ __launch_bounds__(256)
void k_pool() {
    __shared__ unsigned s_p[NB * 32];
    __shared__ float s_ab[64];
    if (threadIdx.x < 64) s_ab[threadIdx.x] = g_bn3[threadIdx.x];
    for (int t = threadIdx.x; t < NB * 32; t += 256) s_p[t] = 0u;
    __syncthreads();

    int pos = blockIdx.x * 256 + threadIdx.x;
    int b = g_bpos[pos];
    const float4* r = reinterpret_cast<const float4*>(g_y3 + (size_t)pos * 32);
#pragma unroll
    for (int c4 = 0; c4 < 8; c4++) {
        float4 t = r[c4];
        float tv[4] = {t.x, t.y, t.z, t.w};
#pragma unroll
        for (int u = 0; u < 4; u++) {
            int c = c4 * 4 + u;
            float v = fmaxf(fmaf(tv[u], s_ab[c], s_ab[32 + c]), 0.f);
            atomicMax(&s_p[b * 32 + c], __float_as_uint(v));   // order-independent
        }
    }
    __syncthreads();
    for (int t = threadIdx.x; t < NB * 32; t += 256) {
        unsigned m = s_p[t];
        if (m) atomicMax(&g_pool[t], m);
    }
}

// ---------------- 8: FC + ReLU ----------------
__global__ void k_fc(const float* __restrict__ Wfc, const float* __restrict__ bfc,
                     float* __restrict__ out)
{
    int bb = blockIdx.x, co = threadIdx.x;
    __shared__ float p[32];
    if (threadIdx.x < 32) p[threadIdx.x] = __uint_as_float(g_pool[bb * 32 + threadIdx.x]);
    __syncthreads();
    float acc = bfc[co];
#pragma unroll
    for (int ci = 0; ci < 32; ci++)
        acc = fmaf(p[ci], Wfc[ci * 128 + co], acc);
    out[bb * 128 + co] = fmaxf(acc, 0.f);
}

// ---------------- launch ----------------
extern "C" void kernel_launch(void* const* d_in, const int* in_sizes, int n_in,
                              void* d_out, int out_size)
{
    const float* feats = (const float*)d_in[0];
    const int*   idx   = (const int*)d_in[1];
    const float* W1    = (const float*)d_in[2];
    const float* g1    = (const float*)d_in[3];
    const float* b1    = (const float*)d_in[4];
    const float* W2    = (const float*)d_in[5];
    const float* g2    = (const float*)d_in[6];
    const float* b2    = (const float*)d_in[7];
    const float* W3    = (const float*)d_in[8];
    const float* g3    = (const float*)d_in[9];
    const float* b3    = (const float*)d_in[10];
    const float* Wfc   = (const float*)d_in[11];
    const float* bfc   = (const float*)d_in[12];
    float* out = (float*)d_out;

    k_scatter<<<NBLK, 256>>>(idx);          // 1
    k_probe<<<NBLK, 256>>>(idx);            // 2 (last block: scan)
    k_rank<<<NBLK, 256>>>(idx);             // 3
    k_conv1<<<NBLK, 256>>>(feats, W1, g1, b1);   // 4  <- ncu capture
    k_conv2<<<NBLK, 256>>>(W2, g2, b2);     // 5
    k_conv3<<<NBLK, 256>>>(W3, g3, b3);     // 6
    k_pool<<<NBLK, 256>>>();                // 7
    k_fc<<<NB, 128>>>(Wfc, bfc, out);       // 8
}

// round 10
// speedup vs baseline: 1.2012x; 1.2012x over previous
#include <cuda_runtime.h>
#include <cstddef>

#define NB    16
#define HH    512
#define WWID  512
#define NPB   20000
#define NPTS  (NB * NPB)          // 320000
#define EPSV  1e-5f
#define NBLK  1250                // NPTS / 256 exactly
#define C2BLK 2500                // conv2 grid (128 pts/block)
#define C3BLK 5000                // conv3 grid (64 pts/block)

// ---------------- scratch ----------------
__device__ int g_map[NB * HH * WWID + 8];          // i+1 encoding; 0 = empty (zero-init; valid across replays)
__device__ int g_nbr[9 * NPTS];                    // i-space tap list (slot-major): (j<<4 | tap)
__device__ int g_cntv[NPTS];
__device__ __align__(16) float g_y1[NPTS * 8];
__device__ __align__(16) float g_y2[NPTS * 16];
__device__ __align__(16) float g_y3[NPTS * 32];
__device__ float g_part[C3BLK * 64];               // [sum(C) | sumsq(C)] rows, stride 64
__device__ float g_bn1[16], g_bn2[32], g_bn3[64];  // folded scale | shift
__device__ unsigned g_pool[NB * 32];
__device__ unsigned g_ctr[4];

#define LAST_BLOCK_GATE(ctr, target, lastvar)                        \
    __threadfence();                                                 \
    __syncthreads();                                                 \
    if (threadIdx.x == 0)                                            \
        lastvar = (atomicAdd(&(ctr), 1u) == (unsigned)(target) - 1u);\
    __syncthreads();

// ---------------- gated-last-block BN fold: ROWS rows of g_part -> bn[2C] ---------
template <int C, int ROWS, int SEGS>
__device__ __forceinline__ void fold_bn(const float* __restrict__ gamma,
                                        const float* __restrict__ beta,
                                        float* __restrict__ bn) {
    __shared__ float s4[SEGS][64];
    int c = threadIdx.x & 63, seg = threadIdx.x >> 6;
    float a = 0.f;
    if (c < 2 * C && seg < SEGS)
        for (int r = seg; r < ROWS; r += SEGS) a += __ldcg(&g_part[r * 64 + c]);
    if (seg < SEGS) s4[seg][c] = a;
    __syncthreads();
    if ((int)threadIdx.x < C) {
        int c0 = threadIdx.x;
        float S = 0.f, Q = 0.f;
#pragma unroll
        for (int k = 0; k < SEGS; k++) { S += s4[k][c0]; Q += s4[k][C + c0]; }
        float m = S / (float)NPTS;
        float var = Q / (float)NPTS - m * m;
        float sc = gamma[c0] * rsqrtf(var + EPSV);
        bn[c0] = sc;
        bn[C + c0] = beta[c0] - m * sc;
    }
}

// ---------------- 1: scatter (i+1) + clear pool/ctr ----------------
__global__ void k_scatter(const int* __restrict__ idx) {
    int i = blockIdx.x * blockDim.x + threadIdx.x;
    if (i < NPTS) {
        int b = idx[3 * i], y = idx[3 * i + 1], x = idx[3 * i + 2];
        g_map[(b << 18) | (y << 9) | x] = i + 1;
    }
    if (i < NB * 32) g_pool[i] = 0u;
    if (i < 4) g_ctr[i] = 0u;
}

// ---------------- 2: probe + conv1 + tap list + stats; gated BN1 fold -------------
__global__ __launch_bounds__(256)
void k_build(const int* __restrict__ idx, const float* __restrict__ feats,
             const float* __restrict__ w1,
             const float* __restrict__ g1, const float* __restrict__ b1)
{
    __shared__ float ws[72];
    __shared__ float s_red[8][16];
    __shared__ bool s_last;
    if (threadIdx.x < 72) ws[threadIdx.x] = w1[threadIdx.x];
    __syncthreads();

    int i = blockIdx.x * 256 + threadIdx.x;
    int b = idx[3 * i], y = idx[3 * i + 1], x = idx[3 * i + 2];
    int base = b << 18;

    int jj[9];
#pragma unroll
    for (int t = 0; t < 9; t++) {
        int ny = y + t / 3 - 1, nx = x + t % 3 - 1;
        bool ok = ((unsigned)ny < (unsigned)HH) && ((unsigned)nx < (unsigned)WWID);
        int nyc = ok ? ny : y, nxc = ok ? nx : x;
        int j = g_map[base + (nyc << 9) + nxc];
        jj[t] = ok ? (j - 1) : -1;
    }

    float acc[8];
#pragma unroll
    for (int c = 0; c < 8; c++) acc[c] = 0.f;
    int cnt = 0;
#pragma unroll
    for (int t = 0; t < 9; t++) {
        if (jj[t] >= 0) {
            g_nbr[cnt * NPTS + i] = (jj[t] << 4) | t;
            cnt++;
            float v = feats[jj[t]];
#pragma unroll
            for (int co = 0; co < 8; co++)
                acc[co] = fmaf(v, ws[t * 8 + co], acc[co]);
        }
    }
    g_cntv[i] = cnt;

    float4* orow = reinterpret_cast<float4*>(g_y1 + (size_t)i * 8);
    orow[0] = make_float4(acc[0], acc[1], acc[2], acc[3]);
    orow[1] = make_float4(acc[4], acc[5], acc[6], acc[7]);

    // block stats
    int lane = threadIdx.x & 31, warp = threadIdx.x >> 5;
#pragma unroll
    for (int co = 0; co < 8; co++) {
        float s = acc[co], q = acc[co] * acc[co];
#pragma unroll
        for (int off = 16; off; off >>= 1) {
            s += __shfl_down_sync(0xffffffffu, s, off);
            q += __shfl_down_sync(0xffffffffu, q, off);
        }
        if (lane == 0) { s_red[warp][co] = s; s_red[warp][8 + co] = q; }
    }
    __syncthreads();
    if (threadIdx.x < 16) {
        float t = 0.f;
#pragma unroll
        for (int w = 0; w < 8; w++) t += s_red[w][threadIdx.x];
        g_part[blockIdx.x * 64 + threadIdx.x] = t;
    }

    LAST_BLOCK_GATE(g_ctr[0], NBLK, s_last);
    if (s_last) fold_bn<8, NBLK, 4>(g1, b1, g_bn1);
}

// ---------------- local counting sort of PPB points by cnt (smem) ----------------
template <int PPB>
__device__ __forceinline__ void local_sort(int blk_base, int* s_ord) {
    __shared__ int s_bin[10], s_base[10];
    if (threadIdx.x < 10) s_bin[threadIdx.x] = 0;
    __syncthreads();
    if (threadIdx.x < PPB) atomicAdd(&s_bin[g_cntv[blk_base + threadIdx.x]], 1);
    __syncthreads();
    if (threadIdx.x == 0) {
        int r = 0;
#pragma unroll
        for (int k = 0; k < 10; k++) { s_base[k] = r; r += s_bin[k]; }
    }
    __syncthreads();
    if (threadIdx.x < PPB) {
        int c = g_cntv[blk_base + threadIdx.x];
        int tk = atomicAdd(&s_base[c], 1);
        s_ord[tk] = threadIdx.x;
    }
    __syncthreads();
}

// ---------------- 3: conv2 (8->16), 4 threads/point; gated BN2 fold ---------------
__global__ __launch_bounds__(512, 3)
void k_conv2(const float* __restrict__ w2,
             const float* __restrict__ g2, const float* __restrict__ b2)
{
    __shared__ float s_ws[9 * 8 * 16];
    __shared__ float s_ab[32];
    __shared__ int s_ord[128];
    __shared__ float s_red[16][64];
    __shared__ bool s_last;
    for (int t = threadIdx.x; t < 9 * 8 * 16; t += 512) s_ws[t] = w2[t];
    if (threadIdx.x < 16) {
        s_ab[threadIdx.x] = g_bn1[threadIdx.x];       // scale8|shift8 packed [0..15]
        s_ab[16 + threadIdx.x] = 0.f;
    }
    local_sort<128>(blockIdx.x * 128, s_ord);

    int q = threadIdx.x & 3;                          // co group: co = 4q+u (COUT=16)
    int lp = s_ord[threadIdx.x >> 2];
    int i = blockIdx.x * 128 + lp;
    int cnt = g_cntv[i];

    float acc[4] = {0.f, 0.f, 0.f, 0.f};
    const float4* f4ws = reinterpret_cast<const float4*>(s_ws);
    for (int s = 0; s < cnt; s++) {
        int p = g_nbr[s * NPTS + i];                  // 8 distinct addrs/warp (broadcast x4)
        int j = p >> 4, tap = p & 15;
        const float4* inr = reinterpret_cast<const float4*>(g_y1 + (size_t)j * 8);
        float4 r0 = inr[0], r1 = inr[1];
        const float4* wq = f4ws + tap * 32 + q;       // ((tap*8+ci)*16 + 4q)/4 = tap*32 + ci*4 + q
        float vv[8] = {r0.x, r0.y, r0.z, r0.w, r1.x, r1.y, r1.z, r1.w};
#pragma unroll
        for (int ci = 0; ci < 8; ci++) {
            float v = fmaxf(fmaf(vv[ci], s_ab[ci], s_ab[8 + ci]), 0.f);
            float4 w4 = wq[ci * 4];
            acc[0] = fmaf(v, w4.x, acc[0]);
            acc[1] = fmaf(v, w4.y, acc[1]);
            acc[2] = fmaf(v, w4.z, acc[2]);
            acc[3] = fmaf(v, w4.w, acc[3]);
        }
    }
    reinterpret_cast<float4*>(g_y2 + (size_t)i * 16)[q] =
        make_float4(acc[0], acc[1], acc[2], acc[3]);

    // stats: combine across the 8 points of the warp (lanes q, q+4, q+8, ...)
    int lane = threadIdx.x & 31, warp = threadIdx.x >> 5;
    float s_[4], q_[4];
#pragma unroll
    for (int u = 0; u < 4; u++) { s_[u] = acc[u]; q_[u] = acc[u] * acc[u]; }
#pragma unroll
    for (int off = 4; off < 32; off <<= 1)
#pragma unroll
        for (int u = 0; u < 4; u++) {
            s_[u] += __shfl_xor_sync(0xffffffffu, s_[u], off);
            q_[u] += __shfl_xor_sync(0xffffffffu, q_[u], off);
        }
    if (lane < 4)
#pragma unroll
        for (int u = 0; u < 4; u++) {
            s_red[warp][lane * 4 + u] = s_[u];
            s_red[warp][16 + lane * 4 + u] = q_[u];
        }
    __syncthreads();
    if (threadIdx.x < 32) {
        float t = 0.f;
#pragma unroll
        for (int w = 0; w < 16; w++) t += s_red[w][threadIdx.x];
        g_part[blockIdx.x * 64 + threadIdx.x] = t;
    }

    LAST_BLOCK_GATE(g_ctr[1], C2BLK, s_last);
    if (s_last) fold_bn<16, C2BLK, 8>(g2, b2, g_bn2);
}

// ---------------- 4: conv3 (16->32), 8 threads/point; gated BN3 fold --------------
__global__ __launch_bounds__(512, 3)
void k_conv3(const float* __restrict__ w3,
             const float* __restrict__ g3, const float* __restrict__ b3)
{
    __shared__ float s_ws[9 * 16 * 32];
    __shared__ float s_ab[32];
    __shared__ int s_ord[64];
    __shared__ float s_red[16][64];
    __shared__ bool s_last;
    for (int t = threadIdx.x; t < 9 * 16 * 32; t += 512) s_ws[t] = w3[t];
    if (threadIdx.x < 32) s_ab[threadIdx.x] = g_bn2[threadIdx.x];  // scale16|shift16
    local_sort<64>(blockIdx.x * 64, s_ord);

    int q = threadIdx.x & 7;                          // co group: co = 4q+u (COUT=32)
    int lp = s_ord[threadIdx.x >> 3];
    int i = blockIdx.x * 64 + lp;
    int cnt = g_cntv[i];

    float acc[4] = {0.f, 0.f, 0.f, 0.f};
    const float4* f4ws = reinterpret_cast<const float4*>(s_ws);
    for (int s = 0; s < cnt; s++) {
        int p = g_nbr[s * NPTS + i];                  // 4 distinct addrs/warp (broadcast x8)
        int j = p >> 4, tap = p & 15;
        const float4* inr = reinterpret_cast<const float4*>(g_y2 + (size_t)j * 16);
        const float4* wq = f4ws + tap * 128 + q;      // ((tap*16+ci)*32 + 4q)/4 = tap*128 + ci*8 + q
#pragma unroll
        for (int ci4 = 0; ci4 < 4; ci4++) {
            float4 v4 = inr[ci4];
            float vv[4] = {v4.x, v4.y, v4.z, v4.w};
#pragma unroll
            for (int u4 = 0; u4 < 4; u4++) {
                int ci = ci4 * 4 + u4;
                float v = fmaxf(fmaf(vv[u4], s_ab[ci], s_ab[16 + ci]), 0.f);
                float4 w4 = wq[ci * 8];
                acc[0] = fmaf(v, w4.x, acc[0]);
                acc[1] = fmaf(v, w4.y, acc[1]);
                acc[2] = fmaf(v, w4.z, acc[2]);
                acc[3] = fmaf(v, w4.w, acc[3]);
            }
        }
    }
    reinterpret_cast<float4*>(g_y3 + (size_t)i * 32)[q] =
        make_float4(acc[0], acc[1], acc[2], acc[3]);

    // stats: combine across the 4 points of the warp (lanes q, q+8, q+16, q+24)
    int lane = threadIdx.x & 31, warp = threadIdx.x >> 5;
    float s_[4], q_[4];
#pragma unroll
    for (int u = 0; u < 4; u++) { s_[u] = acc[u]; q_[u] = acc[u] * acc[u]; }
#pragma unroll
    for (int off = 8; off < 32; off <<= 1)
#pragma unroll
        for (int u = 0; u < 4; u++) {
            s_[u] += __shfl_xor_sync(0xffffffffu, s_[u], off);
            q_[u] += __shfl_xor_sync(0xffffffffu, q_[u], off);
        }
    if (lane < 8)
#pragma unroll
        for (int u = 0; u < 4; u++) {
            s_red[warp][lane * 4 + u] = s_[u];
            s_red[warp][32 + lane * 4 + u] = q_[u];
        }
    __syncthreads();
    if (threadIdx.x < 64) {
        float t = 0.f;
#pragma unroll
        for (int w = 0; w < 16; w++) t += s_red[w][threadIdx.x];
        g_part[blockIdx.x * 64 + threadIdx.x] = t;
    }

    LAST_BLOCK_GATE(g_ctr[2], C3BLK, s_last);
    if (s_last) fold_bn<32, C3BLK, 8>(g3, b3, g_bn3);
}

// ---------------- 5: BN3+ReLU fused segment-max pool ----------------
__global__ void k_pool(const int* __restrict__ idx) {
    int bb = blockIdx.y;
    int l = blockIdx.x * 256 + threadIdx.x;
    __shared__ float s_ab[64];
    if (threadIdx.x < 64) s_ab[threadIdx.x] = g_bn3[threadIdx.x];
    __syncthreads();
    float v[32];
#pragma unroll
    for (int c = 0; c < 32; c++) v[c] = 0.f;
    if (l < NPB) {
        int i = bb * NPB + l;
        const float4* r = reinterpret_cast<const float4*>(g_y3 + (size_t)i * 32);
#pragma unroll
        for (int c4 = 0; c4 < 8; c4++) {
            float4 t = r[c4];
            float tv[4] = {t.x, t.y, t.z, t.w};
#pragma unroll
            for (int u = 0; u < 4; u++) {
                int c = c4 * 4 + u;
                v[c] = fmaxf(fmaf(tv[u], s_ab[c], s_ab[32 + c]), 0.f);
            }
        }
    }
    __shared__ float red[8][32];
    int lane = threadIdx.x & 31, wid = threadIdx.x >> 5;
#pragma unroll
    for (int c = 0; c < 32; c++) {
        float m = v[c];
#pragma unroll
        for (int off = 16; off; off >>= 1)
            m = fmaxf(m, __shfl_down_sync(0xffffffffu, m, off));
        if (lane == 0) red[wid][c] = m;
    }
    __syncthreads();
    if (threadIdx.x < 32) {
        float m = 0.f;
#pragma unroll
        for (int wdx = 0; wdx < 8; wdx++) m = fmaxf(m, red[wdx][threadIdx.x]);
        atomicMax(&g_pool[bb * 32 + threadIdx.x], __float_as_uint(m));
    }
}

// ---------------- 6: FC + ReLU ----------------
__global__ void k_fc(const float* __restrict__ Wfc, const float* __restrict__ bfc,
                     float* __restrict__ out)
{
    int bb = blockIdx.x, co = threadIdx.x;
    __shared__ float p[32];
    if (threadIdx.x < 32) p[threadIdx.x] = __uint_as_float(g_pool[bb * 32 + threadIdx.x]);
    __syncthreads();
    float acc = bfc[co];
#pragma unroll
    for (int ci = 0; ci < 32; ci++)
        acc = fmaf(p[ci], Wfc[ci * 128 + co], acc);
    out[bb * 128 + co] = fmaxf(acc, 0.f);
}

// ---------------- launch ----------------
extern "C" void kernel_launch(void* const* d_in, const int* in_sizes, int n_in,
                              void* d_out, int out_size)
{
    const float* feats = (const float*)d_in[0];
    const int*   idx   = (const int*)d_in[1];
    const float* W1    = (const float*)d_in[2];
    const float* g1    = (const float*)d_in[3];
    const float* b1    = (const float*)d_in[4];
    const float* W2    = (const float*)d_in[5];
    const float* g2    = (const float*)d_in[6];
    const float* b2    = (const float*)d_in[7];
    const float* W3    = (const float*)d_in[8];
    const float* g3    = (const float*)d_in[9];
    const float* b3    = (const float*)d_in[10];
    const float* Wfc   = (const float*)d_in[11];
    const float* bfc   = (const float*)d_in[12];
    float* out = (float*)d_out;

    k_scatter<<<NBLK, 256>>>(idx);                    // 1
    k_build<<<NBLK, 256>>>(idx, feats, W1, g1, b1);   // 2
    k_conv2<<<C2BLK, 512>>>(W2, g2, b2);              // 3
    k_conv3<<<C3BLK, 512>>>(W3, g3, b3);              // 4  <- ncu capture
    dim3 pg((NPB + 255) / 256, NB);
    k_pool<<<pg, 256>>>(idx);                         // 5
    k_fc<<<NB, 128>>>(Wfc, bfc, out);                 // 6
}

// round 11
// speedup vs baseline: 1.2365x; 1.0294x over previous
#include <cuda_runtime.h>
#include <cstddef>

#define NB    16
#define HH    512
#define WWID  512
#define NPB   20000
#define NPTS  (NB * NPB)          // 320000
#define EPSV  1e-5f
#define NBLK  1250                // NPTS / 256 exactly

// ---------------- scratch ----------------
__device__ int g_map[NB * HH * WWID + 8];          // i+1 encoding; 0 = empty (zero-init; valid across replays)
__device__ int g_nbr[9 * NPTS];                    // i-space tap list (slot-major): (j<<4 | tap)
__device__ int g_cntv[NPTS];
__device__ __align__(16) float g_y1[NPTS * 8];
__device__ __align__(16) float g_y2[NPTS * 16];
__device__ __align__(16) float g_y3[NPTS * 32];
__device__ float g_part[NBLK * 64];                // [sum(C) | sumsq(C)] rows, stride 64
__device__ float g_bn1[16], g_bn2[32], g_bn3[64];  // folded scale | shift
__device__ unsigned g_pool[NB * 32];
__device__ unsigned g_ctr[4];

#define LAST_BLOCK_GATE(ctr, target, lastvar)                        \
    __threadfence();                                                 \
    __syncthreads();                                                 \
    if (threadIdx.x == 0)                                            \
        lastvar = (atomicAdd(&(ctr), 1u) == (unsigned)(target) - 1u);\
    __syncthreads();

// ---------------- gated-last-block BN fold ----------------
template <int C>
__device__ __forceinline__ void fold_bn(const float* __restrict__ gamma,
                                        const float* __restrict__ beta,
                                        float* __restrict__ bn) {
    __shared__ float s4[4][64];
    int c = threadIdx.x & 63, seg = threadIdx.x >> 6;
    float a = 0.f;
    if (c < 2 * C && seg < 4)
        for (int r = seg; r < NBLK; r += 4) a += __ldcg(&g_part[r * 64 + c]);
    if (seg < 4) s4[seg][c] = a;
    __syncthreads();
    if ((int)threadIdx.x < C) {
        int c0 = threadIdx.x;
        float S = s4[0][c0] + s4[1][c0] + s4[2][c0] + s4[3][c0];
        float Q = s4[0][C + c0] + s4[1][C + c0] + s4[2][C + c0] + s4[3][C + c0];
        float m = S / (float)NPTS;
        float var = Q / (float)NPTS - m * m;
        float sc = gamma[c0] * rsqrtf(var + EPSV);
        bn[c0] = sc;
        bn[C + c0] = beta[c0] - m * sc;
    }
}

// ---------------- block stats (1 thr/pt): acc[NCH] -> g_part row ----------------
template <int NCH>
__device__ __forceinline__ void block_stats(const float* acc, int blk) {
    __shared__ float s_red[8][2 * NCH];
    int lane = threadIdx.x & 31, warp = threadIdx.x >> 5;
#pragma unroll
    for (int co = 0; co < NCH; co++) {
        float s = acc[co], q = acc[co] * acc[co];
#pragma unroll
        for (int off = 16; off; off >>= 1) {
            s += __shfl_down_sync(0xffffffffu, s, off);
            q += __shfl_down_sync(0xffffffffu, q, off);
        }
        if (lane == 0) { s_red[warp][co] = s; s_red[warp][NCH + co] = q; }
    }
    __syncthreads();
    if (threadIdx.x < 2 * NCH) {
        float t = 0.f;
#pragma unroll
        for (int w = 0; w < 8; w++) t += s_red[w][threadIdx.x];
        g_part[blk * 64 + threadIdx.x] = t;
    }
}

// ---------------- deterministic block-local sort by cnt (256 pts, 256 thr) -------
// s_ord[k] = local point index of k-th point in cnt-sorted order. Fully
// deterministic: warp match ranking + fixed-order warp/bin base scans.
__device__ __forceinline__ void local_sort256(int c, int* s_ord) {
    __shared__ int wcnt[8][10], wbase[8][10], binbase[10];
    int warp = threadIdx.x >> 5, lane = threadIdx.x & 31;
    if (threadIdx.x < 80) wcnt[threadIdx.x >> 1 & 7][0] = 0;  // dummy init below instead
    __syncthreads();
    // proper init
    if (threadIdx.x < 80) wcnt[threadIdx.x / 10][threadIdx.x % 10] = 0;
    __syncthreads();
    unsigned mymask = __match_any_sync(0xffffffffu, c);
    int lrank = __popc(mymask & ((1u << lane) - 1u));
    if (lane == (__ffs(mymask) - 1)) wcnt[warp][c] = __popc(mymask);
    __syncthreads();
    if (threadIdx.x < 80) {
        int w = threadIdx.x / 10, kk = threadIdx.x % 10;
        int s = 0;
        for (int w2 = 0; w2 < w; w2++) s += wcnt[w2][kk];
        wbase[w][kk] = s;
    }
    __syncthreads();
    if (threadIdx.x == 0) {
        int r = 0;
#pragma unroll
        for (int kk = 0; kk < 10; kk++) {
            binbase[kk] = r;
            int t = 0;
#pragma unroll
            for (int w = 0; w < 8; w++) t += wcnt[w][kk];
            r += t;
        }
    }
    __syncthreads();
    s_ord[binbase[c] + wbase[warp][c] + lrank] = threadIdx.x;
    __syncthreads();
}

// ---------------- 1: scatter (i+1) + clear pool/ctr ----------------
__global__ void k_scatter(const int* __restrict__ idx) {
    int i = blockIdx.x * blockDim.x + threadIdx.x;
    if (i < NPTS) {
        int b = idx[3 * i], y = idx[3 * i + 1], x = idx[3 * i + 2];
        g_map[(b << 18) | (y << 9) | x] = i + 1;
    }
    if (i < NB * 32) g_pool[i] = 0u;
    if (i < 4) g_ctr[i] = 0u;
}

// ---------------- 2: probe + conv1 + tap list + stats; gated BN1 fold -------------
__global__ __launch_bounds__(256)
void k_build(const int* __restrict__ idx, const float* __restrict__ feats,
             const float* __restrict__ w1,
             const float* __restrict__ g1, const float* __restrict__ b1)
{
    __shared__ float ws[72];
    __shared__ bool s_last;
    if (threadIdx.x < 72) ws[threadIdx.x] = w1[threadIdx.x];
    __syncthreads();

    int i = blockIdx.x * 256 + threadIdx.x;
    int b = idx[3 * i], y = idx[3 * i + 1], x = idx[3 * i + 2];
    int base = b << 18;

    int jj[9];
#pragma unroll
    for (int t = 0; t < 9; t++) {
        int ny = y + t / 3 - 1, nx = x + t % 3 - 1;
        bool ok = ((unsigned)ny < (unsigned)HH) && ((unsigned)nx < (unsigned)WWID);
        int nyc = ok ? ny : y, nxc = ok ? nx : x;
        int j = g_map[base + (nyc << 9) + nxc];
        jj[t] = ok ? (j - 1) : -1;
    }

    float acc[8];
#pragma unroll
    for (int c = 0; c < 8; c++) acc[c] = 0.f;
    int cnt = 0;
#pragma unroll
    for (int t = 0; t < 9; t++) {
        if (jj[t] >= 0) {
            g_nbr[cnt * NPTS + i] = (jj[t] << 4) | t;
            cnt++;
            float v = feats[jj[t]];
#pragma unroll
            for (int co = 0; co < 8; co++)
                acc[co] = fmaf(v, ws[t * 8 + co], acc[co]);
        }
    }
    g_cntv[i] = cnt;

    float4* orow = reinterpret_cast<float4*>(g_y1 + (size_t)i * 8);
    orow[0] = make_float4(acc[0], acc[1], acc[2], acc[3]);
    orow[1] = make_float4(acc[4], acc[5], acc[6], acc[7]);

    block_stats<8>(acc, blockIdx.x);
    LAST_BLOCK_GATE(g_ctr[0], NBLK, s_last);
    if (s_last) fold_bn<8>(g1, b1, g_bn1);
}

// ---------------- 3: conv2 (8->16), 1 thr/pt, local sort + row pipeline -----------
__global__ __launch_bounds__(256, 4)
void k_conv2(const float* __restrict__ w2,
             const float* __restrict__ g2, const float* __restrict__ b2)
{
    __shared__ float s_ws[9 * 8 * 16];
    __shared__ float s_ab[32];
    __shared__ int s_ord[256];
    __shared__ bool s_last;
    for (int t = threadIdx.x; t < 9 * 8 * 16; t += 256) s_ws[t] = w2[t];
    if (threadIdx.x < 16) s_ab[threadIdx.x] = g_bn1[threadIdx.x];  // scale8|shift8

    int i0 = blockIdx.x * 256 + threadIdx.x;
    int c0 = g_cntv[i0];
    local_sort256(c0, s_ord);        // includes the needed __syncthreads

    int i = blockIdx.x * 256 + s_ord[threadIdx.x];
    int cnt = g_cntv[i];             // cnt >= 1 always (self tap)

    float acc[16];
#pragma unroll
    for (int c = 0; c < 16; c++) acc[c] = 0.f;

    int pcur = g_nbr[i];
    const float4* inr = reinterpret_cast<const float4*>(g_y1 + (size_t)(pcur >> 4) * 8);
    float4 r0 = inr[0], r1 = inr[1];
    int tap = pcur & 15;

    for (int s = 0; s < cnt; s++) {
        // prefetch next row BEFORE this tap's FFMAs
        float4 n0, n1;
        int ntap = 0;
        if (s + 1 < cnt) {
            int pn = g_nbr[(s + 1) * NPTS + i];
            const float4* nr = reinterpret_cast<const float4*>(g_y1 + (size_t)(pn >> 4) * 8);
            n0 = nr[0]; n1 = nr[1];
            ntap = pn & 15;
        }
        const float* wr = s_ws + tap * 128;
        float vv[8] = {r0.x, r0.y, r0.z, r0.w, r1.x, r1.y, r1.z, r1.w};
#pragma unroll
        for (int ci = 0; ci < 8; ci++) {
            float v = fmaxf(fmaf(vv[ci], s_ab[ci], s_ab[8 + ci]), 0.f);
#pragma unroll
            for (int co = 0; co < 16; co++)
                acc[co] = fmaf(v, wr[ci * 16 + co], acc[co]);
        }
        r0 = n0; r1 = n1; tap = ntap;
    }

    float4* orow = reinterpret_cast<float4*>(g_y2 + (size_t)i * 16);
#pragma unroll
    for (int c4 = 0; c4 < 4; c4++)
        orow[c4] = make_float4(acc[4 * c4], acc[4 * c4 + 1], acc[4 * c4 + 2], acc[4 * c4 + 3]);

    block_stats<16>(acc, blockIdx.x);
    LAST_BLOCK_GATE(g_ctr[1], NBLK, s_last);
    if (s_last) fold_bn<16>(g2, b2, g_bn2);
}

// ---------------- 4: conv3 (16->32), 1 thr/pt, local sort + row pipeline ----------
__global__ __launch_bounds__(256, 2)
void k_conv3(const float* __restrict__ w3,
             const float* __restrict__ g3, const float* __restrict__ b3)
{
    __shared__ float s_ws[9 * 16 * 32];
    __shared__ float s_ab[32];
    __shared__ int s_ord[256];
    __shared__ bool s_last;
    for (int t = threadIdx.x; t < 9 * 16 * 32; t += 256) s_ws[t] = w3[t];
    if (threadIdx.x < 32) s_ab[threadIdx.x] = g_bn2[threadIdx.x];  // scale16|shift16

    int i0 = blockIdx.x * 256 + threadIdx.x;
    int c0 = g_cntv[i0];
    local_sort256(c0, s_ord);

    int i = blockIdx.x * 256 + s_ord[threadIdx.x];
    int cnt = g_cntv[i];

    float acc[32];
#pragma unroll
    for (int c = 0; c < 32; c++) acc[c] = 0.f;

    int pcur = g_nbr[i];
    const float4* inr = reinterpret_cast<const float4*>(g_y2 + (size_t)(pcur >> 4) * 16);
    float4 r0 = inr[0], r1 = inr[1], r2 = inr[2], r3 = inr[3];
    int tap = pcur & 15;

    for (int s = 0; s < cnt; s++) {
        float4 n0, n1, n2, n3;
        int ntap = 0;
        if (s + 1 < cnt) {
            int pn = g_nbr[(s + 1) * NPTS + i];
            const float4* nr = reinterpret_cast<const float4*>(g_y2 + (size_t)(pn >> 4) * 16);
            n0 = nr[0]; n1 = nr[1]; n2 = nr[2]; n3 = nr[3];
            ntap = pn & 15;
        }
        const float* wr = s_ws + tap * 512;
        float vv[16] = {r0.x, r0.y, r0.z, r0.w, r1.x, r1.y, r1.z, r1.w,
                        r2.x, r2.y, r2.z, r2.w, r3.x, r3.y, r3.z, r3.w};
#pragma unroll
        for (int ci = 0; ci < 16; ci++) {
            float v = fmaxf(fmaf(vv[ci], s_ab[ci], s_ab[16 + ci]), 0.f);
#pragma unroll
            for (int co = 0; co < 32; co++)
                acc[co] = fmaf(v, wr[ci * 32 + co], acc[co]);
        }
        r0 = n0; r1 = n1; r2 = n2; r3 = n3; tap = ntap;
    }

    float4* orow = reinterpret_cast<float4*>(g_y3 + (size_t)i * 32);
#pragma unroll
    for (int c4 = 0; c4 < 8; c4++)
        orow[c4] = make_float4(acc[4 * c4], acc[4 * c4 + 1], acc[4 * c4 + 2], acc[4 * c4 + 3]);

    block_stats<32>(acc, blockIdx.x);
    LAST_BLOCK_GATE(g_ctr[2], NBLK, s_last);
    if (s_last) fold_bn<32>(g3, b3, g_bn3);
}

// ---------------- 5: BN3+ReLU fused segment-max pool ----------------
__global__ void k_pool(const int* __restrict__ idx) {
    int bb = blockIdx.y;
    int l = blockIdx.x * 256 + threadIdx.x;
    __shared__ float s_ab[64];
    if (threadIdx.x < 64) s_ab[threadIdx.x] = g_bn3[threadIdx.x];
    __syncthreads();
    float v[32];
#pragma unroll
    for (int c = 0; c < 32; c++) v[c] = 0.f;
    if (l < NPB) {
        int i = bb * NPB + l;
        const float4* r = reinterpret_cast<const float4*>(g_y3 + (size_t)i * 32);
#pragma unroll
        for (int c4 = 0; c4 < 8; c4++) {
            float4 t = r[c4];
            float tv[4] = {t.x, t.y, t.z, t.w};
#pragma unroll
            for (int u = 0; u < 4; u++) {
                int c = c4 * 4 + u;
                v[c] = fmaxf(fmaf(tv[u], s_ab[c], s_ab[32 + c]), 0.f);
            }
        }
    }
    __shared__ float red[8][32];
    int lane = threadIdx.x & 31, wid = threadIdx.x >> 5;
#pragma unroll
    for (int c = 0; c < 32; c++) {
        float m = v[c];
#pragma unroll
        for (int off = 16; off; off >>= 1)
            m = fmaxf(m, __shfl_down_sync(0xffffffffu, m, off));
        if (lane == 0) red[wid][c] = m;
    }
    __syncthreads();
    if (threadIdx.x < 32) {
        float m = 0.f;
#pragma unroll
        for (int wdx = 0; wdx < 8; wdx++) m = fmaxf(m, red[wdx][threadIdx.x]);
        atomicMax(&g_pool[bb * 32 + threadIdx.x], __float_as_uint(m));
    }
}

// ---------------- 6: FC + ReLU ----------------
__global__ void k_fc(const float* __restrict__ Wfc, const float* __restrict__ bfc,
                     float* __restrict__ out)
{
    int bb = blockIdx.x, co = threadIdx.x;
    __shared__ float p[32];
    if (threadIdx.x < 32) p[threadIdx.x] = __uint_as_float(g_pool[bb * 32 + threadIdx.x]);
    __syncthreads();
    float acc = bfc[co];
#pragma unroll
    for (int ci = 0; ci < 32; ci++)
        acc = fmaf(p[ci], Wfc[ci * 128 + co], acc);
    out[bb * 128 + co] = fmaxf(acc, 0.f);
}

// ---------------- launch ----------------
extern "C" void kernel_launch(void* const* d_in, const int* in_sizes, int n_in,
                              void* d_out, int out_size)
{
    const float* feats = (const float*)d_in[0];
    const int*   idx   = (const int*)d_in[1];
    const float* W1    = (const float*)d_in[2];
    const float* g1    = (const float*)d_in[3];
    const float* b1    = (const float*)d_in[4];
    const float* W2    = (const float*)d_in[5];
    const float* g2    = (const float*)d_in[6];
    const float* b2    = (const float*)d_in[7];
    const float* W3    = (const float*)d_in[8];
    const float* g3    = (const float*)d_in[9];
    const float* b3    = (const float*)d_in[10];
    const float* Wfc   = (const float*)d_in[11];
    const float* bfc   = (const float*)d_in[12];
    float* out = (float*)d_out;

    k_scatter<<<NBLK, 256>>>(idx);                    // 1
    k_build<<<NBLK, 256>>>(idx, feats, W1, g1, b1);   // 2
    k_conv2<<<NBLK, 256>>>(W2, g2, b2);               // 3
    k_conv3<<<NBLK, 256>>>(W3, g3, b3);               // 4  <- ncu capture
    dim3 pg((NPB + 255) / 256, NB);
    k_pool<<<pg, 256>>>(idx);                         // 5
    k_fc<<<NB, 128>>>(Wfc, bfc, out);                 // 6
}

// round 12
// speedup vs baseline: 1.6109x; 1.3028x over previous
#include <cuda_runtime.h>
#include <cstddef>

#define NB    16
#define HH    512
#define WWID  512
#define NPB   20000
#define NPTS  (NB * NPB)          // 320000
#define EPSV  1e-5f
#define NBLK  1250                // NPTS / 256 exactly

// ---------------- scratch ----------------
__device__ int g_map[NB * HH * WWID + 8];          // i+1 encoding; 0 = empty (zero-init; valid across replays)
__device__ int g_nbr[9 * NPTS];                    // i-space tap list (slot-major): (j<<4 | tap)
__device__ int g_cntv[NPTS];
__device__ int g_maskv[NPTS];                      // 9-bit tap mask
__device__ __align__(16) float g_y1[NPTS * 8];
__device__ __align__(16) float g_y2[NPTS * 16];
__device__ __align__(16) float g_y3[NPTS * 32];
__device__ float g_part[NBLK * 64];                // [sum(C) | sumsq(C)] rows, stride 64
__device__ float g_bn1[16], g_bn2[32], g_bn3[64];  // folded scale | shift
__device__ unsigned g_pool[NB * 32];
__device__ unsigned g_ctr[4];

#define LAST_BLOCK_GATE(ctr, target, lastvar)                        \
    __threadfence();                                                 \
    __syncthreads();                                                 \
    if (threadIdx.x == 0)                                            \
        lastvar = (atomicAdd(&(ctr), 1u) == (unsigned)(target) - 1u);\
    __syncthreads();

// ---------------- gated-last-block BN fold ----------------
template <int C>
__device__ __forceinline__ void fold_bn(const float* __restrict__ gamma,
                                        const float* __restrict__ beta,
                                        float* __restrict__ bn) {
    __shared__ float s4[4][64];
    int c = threadIdx.x & 63, seg = threadIdx.x >> 6;
    float a = 0.f;
    if (c < 2 * C && seg < 4)
        for (int r = seg; r < NBLK; r += 4) a += __ldcg(&g_part[r * 64 + c]);
    if (seg < 4) s4[seg][c] = a;
    __syncthreads();
    if ((int)threadIdx.x < C) {
        int c0 = threadIdx.x;
        float S = s4[0][c0] + s4[1][c0] + s4[2][c0] + s4[3][c0];
        float Q = s4[0][C + c0] + s4[1][C + c0] + s4[2][C + c0] + s4[3][C + c0];
        float m = S / (float)NPTS;
        float var = Q / (float)NPTS - m * m;
        float sc = gamma[c0] * rsqrtf(var + EPSV);
        bn[c0] = sc;
        bn[C + c0] = beta[c0] - m * sc;
    }
}

// ---------------- block stats (1 thr/pt): acc[NCH] -> g_part row ----------------
template <int NCH>
__device__ __forceinline__ void block_stats(const float* acc, int blk) {
    __shared__ float s_red[8][2 * NCH];
    int lane = threadIdx.x & 31, warp = threadIdx.x >> 5;
#pragma unroll
    for (int co = 0; co < NCH; co++) {
        float s = acc[co], q = acc[co] * acc[co];
#pragma unroll
        for (int off = 16; off; off >>= 1) {
            s += __shfl_down_sync(0xffffffffu, s, off);
            q += __shfl_down_sync(0xffffffffu, q, off);
        }
        if (lane == 0) { s_red[warp][co] = s; s_red[warp][NCH + co] = q; }
    }
    __syncthreads();
    if (threadIdx.x < 2 * NCH) {
        float t = 0.f;
#pragma unroll
        for (int w = 0; w < 8; w++) t += s_red[w][threadIdx.x];
        g_part[blk * 64 + threadIdx.x] = t;
    }
}

// ---------------- deterministic block-local sort by 9-bit mask (256 pts) ----------
// s_ord[k] = local index of k-th point in mask-sorted order. No atomics:
// warp match ranking + in-place byte-count prefix + warp-scanned bin bases.
__device__ __forceinline__ void sort_by_mask(int key, unsigned char* wcnt /*8*512*/,
                                             short* tot, short* bb, short* s_ord) {
    int warp = threadIdx.x >> 5, lane = threadIdx.x & 31;
    for (int t = threadIdx.x; t < 8 * 512 / 4; t += 256)
        reinterpret_cast<unsigned*>(wcnt)[t] = 0u;
    __syncthreads();
    unsigned mymask = __match_any_sync(0xffffffffu, key);
    int lrank = __popc(mymask & ((1u << lane) - 1u));
    if (lane == (__ffs(mymask) - 1))
        wcnt[warp * 512 + key] = (unsigned char)__popc(mymask);
    __syncthreads();
    // per-key exclusive prefix over warps (in place), total per key
    for (int k = threadIdx.x; k < 512; k += 256) {
        int run = 0;
#pragma unroll
        for (int w = 0; w < 8; w++) {
            int c = wcnt[w * 512 + k];
            wcnt[w * 512 + k] = (unsigned char)run;
            run += c;
        }
        tot[k] = (short)run;
    }
    __syncthreads();
    // exclusive scan over 512 keys (warp 0, 16 keys/lane)
    if (threadIdx.x < 32) {
        int l = threadIdx.x;
        int s = 0;
#pragma unroll
        for (int q = 0; q < 16; q++) { bb[l * 16 + q] = (short)s; s += tot[l * 16 + q]; }
        int chunk = s, off = chunk;
#pragma unroll
        for (int d = 1; d < 32; d <<= 1) {
            int n = __shfl_up_sync(0xffffffffu, off, d);
            if (l >= d) off += n;
        }
        off -= chunk;
#pragma unroll
        for (int q = 0; q < 16; q++) bb[l * 16 + q] = (short)(bb[l * 16 + q] + off);
    }
    __syncthreads();
    s_ord[bb[key] + wcnt[warp * 512 + key] + lrank] = (short)threadIdx.x;
    __syncthreads();
}

// ---------------- 1: scatter (i+1) + clear pool/ctr ----------------
__global__ void k_scatter(const int* __restrict__ idx) {
    int i = blockIdx.x * blockDim.x + threadIdx.x;
    if (i < NPTS) {
        int b = idx[3 * i], y = idx[3 * i + 1], x = idx[3 * i + 2];
        g_map[(b << 18) | (y << 9) | x] = i + 1;
    }
    if (i < NB * 32) g_pool[i] = 0u;
    if (i < 4) g_ctr[i] = 0u;
}

// ---------------- 2: probe + conv1 + tap list + mask + stats; gated BN1 fold ------
__global__ __launch_bounds__(256)
void k_build(const int* __restrict__ idx, const float* __restrict__ feats,
             const float* __restrict__ w1,
             const float* __restrict__ g1, const float* __restrict__ b1)
{
    __shared__ float ws[72];
    __shared__ bool s_last;
    if (threadIdx.x < 72) ws[threadIdx.x] = w1[threadIdx.x];
    __syncthreads();

    int i = blockIdx.x * 256 + threadIdx.x;
    int b = idx[3 * i], y = idx[3 * i + 1], x = idx[3 * i + 2];
    int base = b << 18;

    int jj[9];
#pragma unroll
    for (int t = 0; t < 9; t++) {
        int ny = y + t / 3 - 1, nx = x + t % 3 - 1;
        bool ok = ((unsigned)ny < (unsigned)HH) && ((unsigned)nx < (unsigned)WWID);
        int nyc = ok ? ny : y, nxc = ok ? nx : x;
        int j = g_map[base + (nyc << 9) + nxc];
        jj[t] = ok ? (j - 1) : -1;
    }

    float acc[8];
#pragma unroll
    for (int c = 0; c < 8; c++) acc[c] = 0.f;
    int cnt = 0, mask = 0;
#pragma unroll
    for (int t = 0; t < 9; t++) {
        if (jj[t] >= 0) {
            g_nbr[cnt * NPTS + i] = (jj[t] << 4) | t;
            cnt++;
            mask |= (1 << t);
            float v = feats[jj[t]];
#pragma unroll
            for (int co = 0; co < 8; co++)
                acc[co] = fmaf(v, ws[t * 8 + co], acc[co]);
        }
    }
    g_cntv[i] = cnt;
    g_maskv[i] = mask;

    float4* orow = reinterpret_cast<float4*>(g_y1 + (size_t)i * 8);
    orow[0] = make_float4(acc[0], acc[1], acc[2], acc[3]);
    orow[1] = make_float4(acc[4], acc[5], acc[6], acc[7]);

    block_stats<8>(acc, blockIdx.x);
    LAST_BLOCK_GATE(g_ctr[0], NBLK, s_last);
    if (s_last) fold_bn<8>(g1, b1, g_bn1);
}

// ---------------- 3: conv2 (8->16), mask-sorted warps; gated BN2 fold -------------
__global__ __launch_bounds__(256, 4)
void k_conv2(const float* __restrict__ w2,
             const float* __restrict__ g2, const float* __restrict__ b2)
{
    __shared__ float s_ws[9 * 132];            // tap stride 132 floats (pad)
    __shared__ float s_ab[32];
    __shared__ unsigned char s_wcnt[8 * 512];
    __shared__ short s_tot[512], s_bb[512], s_ord[256];
    __shared__ bool s_last;
    for (int t = threadIdx.x; t < 9 * 128; t += 256)
        s_ws[(t >> 7) * 132 + (t & 127)] = w2[t];
    if (threadIdx.x < 16) s_ab[threadIdx.x] = g_bn1[threadIdx.x];   // scale8|shift8

    int i0 = blockIdx.x * 256 + threadIdx.x;
    int key = g_maskv[i0];
    sort_by_mask(key, s_wcnt, s_tot, s_bb, s_ord);   // includes syncthreads

    int i = blockIdx.x * 256 + s_ord[threadIdx.x];
    int cnt = g_cntv[i];

    float acc[16];
#pragma unroll
    for (int c = 0; c < 16; c++) acc[c] = 0.f;

    for (int s = 0; s < cnt; s++) {
        int p = g_nbr[s * NPTS + i];
        int j = p >> 4, tap = p & 15;
        const float4* inr = reinterpret_cast<const float4*>(g_y1 + (size_t)j * 8);
        float4 r0 = inr[0], r1 = inr[1];
        const float* wr = s_ws + tap * 132;          // warp-uniform (mask-sorted)
        float vv[8] = {r0.x, r0.y, r0.z, r0.w, r1.x, r1.y, r1.z, r1.w};
#pragma unroll
        for (int ci = 0; ci < 8; ci++) {
            float v = fmaxf(fmaf(vv[ci], s_ab[ci], s_ab[8 + ci]), 0.f);
#pragma unroll
            for (int co = 0; co < 16; co++)
                acc[co] = fmaf(v, wr[ci * 16 + co], acc[co]);
        }
    }

    float4* orow = reinterpret_cast<float4*>(g_y2 + (size_t)i * 16);
#pragma unroll
    for (int c4 = 0; c4 < 4; c4++)
        orow[c4] = make_float4(acc[4 * c4], acc[4 * c4 + 1], acc[4 * c4 + 2], acc[4 * c4 + 3]);

    block_stats<16>(acc, blockIdx.x);
    LAST_BLOCK_GATE(g_ctr[1], NBLK, s_last);
    if (s_last) fold_bn<16>(g2, b2, g_bn2);
}

// ---------------- 4: conv3 (16->32), mask-sorted warps; gated BN3 fold ------------
__global__ __launch_bounds__(256, 3)
void k_conv3(const float* __restrict__ w3,
             const float* __restrict__ g3, const float* __restrict__ b3)
{
    __shared__ float s_ws[9 * 516];            // tap stride 516 floats (pad)
    __shared__ float s_ab[32];
    __shared__ unsigned char s_wcnt[8 * 512];
    __shared__ short s_tot[512], s_bb[512], s_ord[256];
    __shared__ bool s_last;
    for (int t = threadIdx.x; t < 9 * 512; t += 256)
        s_ws[(t >> 9) * 516 + (t & 511)] = w3[t];
    if (threadIdx.x < 32) s_ab[threadIdx.x] = g_bn2[threadIdx.x];   // scale16|shift16

    int i0 = blockIdx.x * 256 + threadIdx.x;
    int key = g_maskv[i0];
    sort_by_mask(key, s_wcnt, s_tot, s_bb, s_ord);

    int i = blockIdx.x * 256 + s_ord[threadIdx.x];
    int cnt = g_cntv[i];

    float acc[32];
#pragma unroll
    for (int c = 0; c < 32; c++) acc[c] = 0.f;

    for (int s = 0; s < cnt; s++) {
        int p = g_nbr[s * NPTS + i];
        int j = p >> 4, tap = p & 15;
        const float4* inr = reinterpret_cast<const float4*>(g_y2 + (size_t)j * 16);
        float4 r0 = inr[0], r1 = inr[1], r2 = inr[2], r3 = inr[3];
        const float* wr = s_ws + tap * 516;          // warp-uniform (mask-sorted)
        float vv[16] = {r0.x, r0.y, r0.z, r0.w, r1.x, r1.y, r1.z, r1.w,
                        r2.x, r2.y, r2.z, r2.w, r3.x, r3.y, r3.z, r3.w};
#pragma unroll
        for (int ci = 0; ci < 16; ci++) {
            float v = fmaxf(fmaf(vv[ci], s_ab[ci], s_ab[16 + ci]), 0.f);
#pragma unroll
            for (int co = 0; co < 32; co++)
                acc[co] = fmaf(v, wr[ci * 32 + co], acc[co]);
        }
    }

    float4* orow = reinterpret_cast<float4*>(g_y3 + (size_t)i * 32);
#pragma unroll
    for (int c4 = 0; c4 < 8; c4++)
        orow[c4] = make_float4(acc[4 * c4], acc[4 * c4 + 1], acc[4 * c4 + 2], acc[4 * c4 + 3]);

    block_stats<32>(acc, blockIdx.x);
    LAST_BLOCK_GATE(g_ctr[2], NBLK, s_last);
    if (s_last) fold_bn<32>(g3, b3, g_bn3);
}

// ---------------- 5: BN3+ReLU fused segment-max pool ----------------
__global__ void k_pool(const int* __restrict__ idx) {
    int bb = blockIdx.y;
    int l = blockIdx.x * 256 + threadIdx.x;
    __shared__ float s_ab[64];
    if (threadIdx.x < 64) s_ab[threadIdx.x] = g_bn3[threadIdx.x];
    __syncthreads();
    float v[32];
#pragma unroll
    for (int c = 0; c < 32; c++) v[c] = 0.f;
    if (l < NPB) {
        int i = bb * NPB + l;
        const float4* r = reinterpret_cast<const float4*>(g_y3 + (size_t)i * 32);
#pragma unroll
        for (int c4 = 0; c4 < 8; c4++) {
            float4 t = r[c4];
            float tv[4] = {t.x, t.y, t.z, t.w};
#pragma unroll
            for (int u = 0; u < 4; u++) {
                int c = c4 * 4 + u;
                v[c] = fmaxf(fmaf(tv[u], s_ab[c], s_ab[32 + c]), 0.f);
            }
        }
    }
    __shared__ float red[8][32];
    int lane = threadIdx.x & 31, wid = threadIdx.x >> 5;
#pragma unroll
    for (int c = 0; c < 32; c++) {
        float m = v[c];
#pragma unroll
        for (int off = 16; off; off >>= 1)
            m = fmaxf(m, __shfl_down_sync(0xffffffffu, m, off));
        if (lane == 0) red[wid][c] = m;
    }
    __syncthreads();
    if (threadIdx.x < 32) {
        float m = 0.f;
#pragma unroll
        for (int wdx = 0; wdx < 8; wdx++) m = fmaxf(m, red[wdx][threadIdx.x]);
        atomicMax(&g_pool[bb * 32 + threadIdx.x], __float_as_uint(m));
    }
}

// ---------------- 6: FC + ReLU ----------------
__global__ void k_fc(const float* __restrict__ Wfc, const float* __restrict__ bfc,
                     float* __restrict__ out)
{
    int bb = blockIdx.x, co = threadIdx.x;
    __shared__ float p[32];
    if (threadIdx.x < 32) p[threadIdx.x] = __uint_as_float(g_pool[bb * 32 + threadIdx.x]);
    __syncthreads();
    float acc = bfc[co];
#pragma unroll
    for (int ci = 0; ci < 32; ci++)
        acc = fmaf(p[ci], Wfc[ci * 128 + co], acc);
    out[bb * 128 + co] = fmaxf(acc, 0.f);
}

// ---------------- launch ----------------
extern "C" void kernel_launch(void* const* d_in, const int* in_sizes, int n_in,
                              void* d_out, int out_size)
{
    const float* feats = (const float*)d_in[0];
    const int*   idx   = (const int*)d_in[1];
    const float* W1    = (const float*)d_in[2];
    const float* g1    = (const float*)d_in[3];
    const float* b1    = (const float*)d_in[4];
    const float* W2    = (const float*)d_in[5];
    const float* g2    = (const float*)d_in[6];
    const float* b2    = (const float*)d_in[7];
    const float* W3    = (const float*)d_in[8];
    const float* g3    = (const float*)d_in[9];
    const float* b3    = (const float*)d_in[10];
    const float* Wfc   = (const float*)d_in[11];
    const float* bfc   = (const float*)d_in[12];
    float* out = (float*)d_out;

    k_scatter<<<NBLK, 256>>>(idx);                    // 1
    k_build<<<NBLK, 256>>>(idx, feats, W1, g1, b1);   // 2
    k_conv2<<<NBLK, 256>>>(W2, g2, b2);               // 3
    k_conv3<<<NBLK, 256>>>(W3, g3, b3);               // 4  <- ncu capture
    dim3 pg((NPB + 255) / 256, NB);
    k_pool<<<pg, 256>>>(idx);                         // 5
    k_fc<<<NB, 128>>>(Wfc, bfc, out);                 // 6
}